// round 1
// baseline (speedup 1.0000x reference)
#include <cuda_runtime.h>

// Problem-fixed geometry (dataset shapes are constant for this problem)
#define Hh 100
#define Ww 136
#define HW (Hh * Ww)        // 13600
#define OH (2 * Hh)         // 200
#define OW (2 * Ww)         // 272
#define OHW (OH * OW)       // 54400
#define NP 169              // params per instance
#define MAXI 512            // max instances supported (actual n = 500)

// Scratch (device globals: allocation-free, graph-capture safe)
__device__ float g_logits[MAXI * HW];   // ~27.8 MB
__device__ float g_inter[MAXI];
__device__ float g_ux[MAXI];
__device__ float g_ut[MAXI];

// ---------------------------------------------------------------------------
// Kernel A: per-instance dynamic mask head (3-layer 1x1 conv MLP) -> logits
// One block per instance; params cached in SMEM; 4 pixels per thread for ILP
// and weight-load amortization.
// ---------------------------------------------------------------------------
__global__ __launch_bounds__(256) void logits_kernel(
    const float* __restrict__ feats,    // [N, 8, H, W]
    const float* __restrict__ params,   // [n, 169]
    const float* __restrict__ locs,     // [n, 2]
    const int*   __restrict__ im_inds,  // [n]
    const int*   __restrict__ fpn)      // [n]
{
    const int inst = blockIdx.x;
    const int tid  = threadIdx.x;

    __shared__ float sp[NP];
    if (tid < NP) sp[tid] = params[inst * NP + tid];
    __syncthreads();

    const float cx = locs[inst * 2 + 0];
    const float cy = locs[inst * 2 + 1];
    const int   lvl = fpn[inst];
    const float inv_soi = 1.0f / (float)(8 << lvl);   // exact power-of-two recip
    const float* __restrict__ fb = feats + (size_t)im_inds[inst] * 8 * HW;
    float* __restrict__ Lg = g_logits + (size_t)inst * HW;

    for (int p0 = tid; p0 < HW; p0 += 1024) {
        float dx[4], dy[4], f[4][8], h0[4][8], h1[4][8];
        int pp[4];

        #pragma unroll
        for (int k = 0; k < 4; k++) {
            int p  = p0 + k * 256;
            int pc = (p < HW) ? p : (HW - 1);
            pp[k] = p;
            int py = pc / Ww;
            int px = pc - py * Ww;
            dx[k] = (cx - (float)(px * 8 + 4)) * inv_soi;
            dy[k] = (cy - (float)(py * 8 + 4)) * inv_soi;
            #pragma unroll
            for (int c = 0; c < 8; c++) f[k][c] = fb[c * HW + pc];
        }

        // layer 0: (2+8) -> 8, relu
        #pragma unroll
        for (int j = 0; j < 8; j++) {
            const float wx = sp[j * 10 + 0];
            const float wy = sp[j * 10 + 1];
            const float b  = sp[152 + j];
            float wc[8];
            #pragma unroll
            for (int c = 0; c < 8; c++) wc[c] = sp[j * 10 + 2 + c];
            #pragma unroll
            for (int k = 0; k < 4; k++) {
                float a = fmaf(wx, dx[k], fmaf(wy, dy[k], b));
                #pragma unroll
                for (int c = 0; c < 8; c++) a = fmaf(wc[c], f[k][c], a);
                h0[k][j] = fmaxf(a, 0.0f);
            }
        }

        // layer 1: 8 -> 8, relu
        #pragma unroll
        for (int j = 0; j < 8; j++) {
            const float b = sp[160 + j];
            float wc[8];
            #pragma unroll
            for (int c = 0; c < 8; c++) wc[c] = sp[80 + j * 8 + c];
            #pragma unroll
            for (int k = 0; k < 4; k++) {
                float a = b;
                #pragma unroll
                for (int c = 0; c < 8; c++) a = fmaf(wc[c], h0[k][c], a);
                h1[k][j] = fmaxf(a, 0.0f);
            }
        }

        // layer 2: 8 -> 1
        {
            const float b2 = sp[168];
            float wc[8];
            #pragma unroll
            for (int c = 0; c < 8; c++) wc[c] = sp[144 + c];
            #pragma unroll
            for (int k = 0; k < 4; k++) {
                float a = b2;
                #pragma unroll
                for (int c = 0; c < 8; c++) a = fmaf(wc[c], h1[k][c], a);
                if (pp[k] < HW) Lg[pp[k]] = a;
            }
        }
    }
}

// ---------------------------------------------------------------------------
// Kernel B: aligned_bilinear(x2) + sigmoid + per-instance dice partial sums.
// One block per instance -> L1-resident logit tile, deterministic reduction.
// out[oy][ox] = up[max(oy-1,0)][max(ox-1,0)], up = align_corners 2x bilinear
// on edge-padded logits (clamped row/col indices).
// ---------------------------------------------------------------------------
__global__ __launch_bounds__(256) void dice_kernel(const float* __restrict__ gt)
{
    const int inst = blockIdx.x;
    const float* __restrict__ L = g_logits + (size_t)inst * HW;
    const float* __restrict__ T = gt + (size_t)inst * OHW;

    float si = 0.0f, sx = 0.0f, st = 0.0f;

    for (int p = threadIdx.x; p < OHW; p += 256) {
        int oy = p / OW;
        int ox = p - oy * OW;
        int j = (oy > 0) ? (oy - 1) : 0;
        int i = (ox > 0) ? (ox - 1) : 0;
        int y0 = j >> 1, x0 = i >> 1;
        int y1 = min(y0 + 1, Hh - 1);
        int x1 = min(x0 + 1, Ww - 1);

        const float* r0 = L + y0 * Ww;
        float v;
        float a00 = r0[x0];
        if ((j & 1) == 0) {
            v = (i & 1) ? 0.5f * (a00 + r0[x1]) : a00;
        } else {
            const float* r1 = L + y1 * Ww;
            if (i & 1) v = 0.25f * ((a00 + r0[x1]) + (r1[x0] + r1[x1]));
            else       v = 0.5f * (a00 + r1[x0]);
        }

        float s = 1.0f / (1.0f + __expf(-v));
        float t = T[p];
        si = fmaf(s, t, si);
        sx = fmaf(s, s, sx);
        st = fmaf(t, t, st);
    }

    // block reduction (8 warps)
    __shared__ float sm[3][8];
    int lane = threadIdx.x & 31;
    int wid  = threadIdx.x >> 5;
    #pragma unroll
    for (int o = 16; o; o >>= 1) {
        si += __shfl_down_sync(0xffffffffu, si, o);
        sx += __shfl_down_sync(0xffffffffu, sx, o);
        st += __shfl_down_sync(0xffffffffu, st, o);
    }
    if (lane == 0) { sm[0][wid] = si; sm[1][wid] = sx; sm[2][wid] = st; }
    __syncthreads();
    if (wid == 0) {
        si = (lane < 8) ? sm[0][lane] : 0.0f;
        sx = (lane < 8) ? sm[1][lane] : 0.0f;
        st = (lane < 8) ? sm[2][lane] : 0.0f;
        #pragma unroll
        for (int o = 4; o; o >>= 1) {
            si += __shfl_down_sync(0xffffffffu, si, o);
            sx += __shfl_down_sync(0xffffffffu, sx, o);
            st += __shfl_down_sync(0xffffffffu, st, o);
        }
        if (lane == 0) {
            g_inter[inst] = si;
            g_ux[inst]    = sx;
            g_ut[inst]    = st;
        }
    }
}

// ---------------------------------------------------------------------------
// Kernel C: dice loss per instance + mean
// ---------------------------------------------------------------------------
__global__ __launch_bounds__(512) void loss_kernel(float* __restrict__ out, int n)
{
    __shared__ float sm[16];
    float acc = 0.0f;
    for (int i = threadIdx.x; i < n; i += 512) {
        float u = g_ux[i] + g_ut[i] + 1e-5f;
        acc += 1.0f - 2.0f * g_inter[i] / u;
    }
    int lane = threadIdx.x & 31;
    int wid  = threadIdx.x >> 5;
    #pragma unroll
    for (int o = 16; o; o >>= 1) acc += __shfl_down_sync(0xffffffffu, acc, o);
    if (lane == 0) sm[wid] = acc;
    __syncthreads();
    if (wid == 0) {
        acc = (lane < 16) ? sm[lane] : 0.0f;
        #pragma unroll
        for (int o = 8; o; o >>= 1) acc += __shfl_down_sync(0xffffffffu, acc, o);
        if (lane == 0) out[0] = acc / (float)n;
    }
}

// ---------------------------------------------------------------------------
// Launch: metadata order is
//   0 mask_feats f32 [2,8,100,136]   1 mask_head_params f32 [n,169]
//   2 locations_inst f32 [n,2]       3 gt_bitmasks f32 [n,1,200,272]
//   4 im_inds i32 [n]                5 fpn_levels i32 [n]
//   6 mask_feat_stride (unused; fixed 8)
// ---------------------------------------------------------------------------
extern "C" void kernel_launch(void* const* d_in, const int* in_sizes, int n_in,
                              void* d_out, int out_size)
{
    const float* feats   = (const float*)d_in[0];
    const float* params  = (const float*)d_in[1];
    const float* locs    = (const float*)d_in[2];
    const float* gt      = (const float*)d_in[3];
    const int*   im_inds = (const int*)d_in[4];
    const int*   fpn     = (const int*)d_in[5];

    int n = in_sizes[1] / NP;   // 500
    if (n > MAXI) n = MAXI;

    logits_kernel<<<n, 256>>>(feats, params, locs, im_inds, fpn);
    dice_kernel<<<n, 256>>>(gt);
    loss_kernel<<<1, 512>>>((float*)d_out, n);
}

// round 2
// speedup vs baseline: 1.4496x; 1.4496x over previous
#include <cuda_runtime.h>

#define Hh 100
#define Ww 136
#define HW (Hh * Ww)        // 13600
#define OH (2 * Hh)         // 200
#define OW (2 * Ww)         // 272
#define OHW (OH * OW)       // 54400
#define NP 169
#define MAXI 512

typedef unsigned long long ull;

__device__ float g_logits[MAXI * HW];
__device__ float g_inter[MAXI];
__device__ float g_ux[MAXI];
__device__ float g_ut[MAXI];

// ---- packed f32x2 helpers (sm_100+) ----
__device__ __forceinline__ ull pk2(float lo, float hi) {
    ull r; asm("mov.b64 %0, {%1,%2};" : "=l"(r) : "f"(lo), "f"(hi)); return r;
}
__device__ __forceinline__ ull fma2(ull a, ull b, ull c) {
    ull d; asm("fma.rn.f32x2 %0, %1, %2, %3;" : "=l"(d) : "l"(a), "l"(b), "l"(c)); return d;
}
__device__ __forceinline__ ull relu2(ull a) {
    float x, y;
    asm("mov.b64 {%0,%1}, %2;" : "=f"(x), "=f"(y) : "l"(a));
    x = fmaxf(x, 0.0f); y = fmaxf(y, 0.0f);
    ull r; asm("mov.b64 %0, {%1,%2};" : "=l"(r) : "f"(x), "f"(y)); return r;
}
__device__ __forceinline__ void upk2(ull a, float& x, float& y) {
    asm("mov.b64 {%0,%1}, %2;" : "=f"(x), "=f"(y) : "l"(a));
}

// ---------------------------------------------------------------------------
// Kernel A: dynamic mask head -> logits. One block per instance.
// 4 pixels/thread as two f32x2 pairs; weights pre-duplicated in SMEM,
// fetched as LDS.128 (2 packed weights per load).
// ---------------------------------------------------------------------------
__global__ __launch_bounds__(256, 2) void logits_kernel(
    const float* __restrict__ feats,
    const float* __restrict__ params,
    const float* __restrict__ locs,
    const int*   __restrict__ im_inds,
    const int*   __restrict__ fpn)
{
    const int inst = blockIdx.x;
    const int tid  = threadIdx.x;

    // packed (duplicated) weights: sw0[j][0..9]=w, [10]=bias ; sw1[j][0..7]=w,[8]=bias
    __shared__ __align__(16) ull sw0[8][12];
    __shared__ __align__(16) ull sw1[8][10];
    __shared__ __align__(16) ull sw2[10];

    for (int i = tid; i < NP; i += 256) {
        float w = params[inst * NP + i];
        ull d = pk2(w, w);
        if      (i < 80)  sw0[i / 10][i % 10] = d;
        else if (i < 144) { int k = i - 80; sw1[k >> 3][k & 7] = d; }
        else if (i < 152) sw2[i - 144] = d;
        else if (i < 160) sw0[i - 152][10] = d;
        else if (i < 168) sw1[i - 160][8] = d;
        else              sw2[8] = d;
    }
    __syncthreads();

    const float cx = locs[inst * 2 + 0];
    const float cy = locs[inst * 2 + 1];
    const float inv_soi = 1.0f / (float)(8 << fpn[inst]);
    const float step = -8.0f * inv_soi;
    const float* __restrict__ fb = feats + (size_t)im_inds[inst] * 8 * HW;
    float* __restrict__ Lg = g_logits + (size_t)inst * HW;

    const int NQ = HW / 4;   // 3400, Ww%4==0 so quads never cross rows
    for (int q = tid; q < NQ; q += 256) {
        const int p  = q * 4;
        const int py = p / Ww;
        const int px = p - py * Ww;
        const float dyv = (cy - (float)(py * 8 + 4)) * inv_soi;
        const float dxb = (cx - (float)(px * 8 + 4)) * inv_soi;
        const ull dy2 = pk2(dyv, dyv);
        const ull dx0 = pk2(dxb, dxb + step);
        const ull dx1 = pk2(dxb + 2.0f * step, dxb + 3.0f * step);

        ull f0[8], f1[8];
        #pragma unroll
        for (int c = 0; c < 8; c++) {
            float4 v = *(const float4*)&fb[c * HW + p];
            f0[c] = pk2(v.x, v.y);
            f1[c] = pk2(v.z, v.w);
        }

        // layer 0: 10 -> 8, relu
        ull h0a[8], h0b[8];
        #pragma unroll
        for (int j = 0; j < 8; j++) {
            const ulonglong2* r = (const ulonglong2*)sw0[j];
            ulonglong2 wA = r[0], wB = r[1], wC = r[2], wD = r[3], wE = r[4];
            ull bias = sw0[j][10];
            ull a0 = fma2(wA.y, dy2, bias);  a0 = fma2(wA.x, dx0, a0);
            ull a1 = fma2(wA.y, dy2, bias);  a1 = fma2(wA.x, dx1, a1);
            a0 = fma2(wB.x, f0[0], a0);  a1 = fma2(wB.x, f1[0], a1);
            a0 = fma2(wB.y, f0[1], a0);  a1 = fma2(wB.y, f1[1], a1);
            a0 = fma2(wC.x, f0[2], a0);  a1 = fma2(wC.x, f1[2], a1);
            a0 = fma2(wC.y, f0[3], a0);  a1 = fma2(wC.y, f1[3], a1);
            a0 = fma2(wD.x, f0[4], a0);  a1 = fma2(wD.x, f1[4], a1);
            a0 = fma2(wD.y, f0[5], a0);  a1 = fma2(wD.y, f1[5], a1);
            a0 = fma2(wE.x, f0[6], a0);  a1 = fma2(wE.x, f1[6], a1);
            a0 = fma2(wE.y, f0[7], a0);  a1 = fma2(wE.y, f1[7], a1);
            h0a[j] = relu2(a0);
            h0b[j] = relu2(a1);
        }

        // layer 1: 8 -> 8, relu
        ull h1a[8], h1b[8];
        #pragma unroll
        for (int j = 0; j < 8; j++) {
            const ulonglong2* r = (const ulonglong2*)sw1[j];
            ulonglong2 wA = r[0], wB = r[1], wC = r[2], wD = r[3];
            ull bias = sw1[j][8];
            ull a0 = fma2(wA.x, h0a[0], bias);  ull a1 = fma2(wA.x, h0b[0], bias);
            a0 = fma2(wA.y, h0a[1], a0);  a1 = fma2(wA.y, h0b[1], a1);
            a0 = fma2(wB.x, h0a[2], a0);  a1 = fma2(wB.x, h0b[2], a1);
            a0 = fma2(wB.y, h0a[3], a0);  a1 = fma2(wB.y, h0b[3], a1);
            a0 = fma2(wC.x, h0a[4], a0);  a1 = fma2(wC.x, h0b[4], a1);
            a0 = fma2(wC.y, h0a[5], a0);  a1 = fma2(wC.y, h0b[5], a1);
            a0 = fma2(wD.x, h0a[6], a0);  a1 = fma2(wD.x, h0b[6], a1);
            a0 = fma2(wD.y, h0a[7], a0);  a1 = fma2(wD.y, h0b[7], a1);
            h1a[j] = relu2(a0);
            h1b[j] = relu2(a1);
        }

        // layer 2: 8 -> 1
        {
            const ulonglong2* r = (const ulonglong2*)sw2;
            ulonglong2 wA = r[0], wB = r[1], wC = r[2], wD = r[3];
            ull bias = sw2[8];
            ull a0 = fma2(wA.x, h1a[0], bias);  ull a1 = fma2(wA.x, h1b[0], bias);
            a0 = fma2(wA.y, h1a[1], a0);  a1 = fma2(wA.y, h1b[1], a1);
            a0 = fma2(wB.x, h1a[2], a0);  a1 = fma2(wB.x, h1b[2], a1);
            a0 = fma2(wB.y, h1a[3], a0);  a1 = fma2(wB.y, h1b[3], a1);
            a0 = fma2(wC.x, h1a[4], a0);  a1 = fma2(wC.x, h1b[4], a1);
            a0 = fma2(wC.y, h1a[5], a0);  a1 = fma2(wC.y, h1b[5], a1);
            a0 = fma2(wD.x, h1a[6], a0);  a1 = fma2(wD.x, h1b[6], a1);
            a0 = fma2(wD.y, h1a[7], a0);  a1 = fma2(wD.y, h1b[7], a1);
            float4 o;
            upk2(a0, o.x, o.y);
            upk2(a1, o.z, o.w);
            *(float4*)&Lg[p] = o;
        }
    }
}

// ---------------------------------------------------------------------------
// Kernel B: 2x aligned-bilinear + sigmoid + dice partials.
// One block per instance; full logit tile staged in dynamic SMEM; 4-pixel
// quads with float4 gt loads.
// ---------------------------------------------------------------------------
__global__ __launch_bounds__(256) void dice_kernel(const float* __restrict__ gt)
{
    extern __shared__ float sL[];   // HW floats = 54.4 KB
    const int inst = blockIdx.x;
    const float* __restrict__ L = g_logits + (size_t)inst * HW;
    const float* __restrict__ T = gt + (size_t)inst * OHW;

    for (int i = threadIdx.x; i < HW; i += 256) sL[i] = L[i];
    __syncthreads();

    float si = 0.0f, sx = 0.0f, st = 0.0f;

    const int NQ = OHW / 4;       // 13600 (OW%4==0, quads never cross rows)
    for (int q = threadIdx.x; q < NQ; q += 256) {
        const int oy = q / (OW / 4);
        const int ox = (q - oy * (OW / 4)) * 4;
        const int j  = (oy > 0) ? (oy - 1) : 0;
        const int y0 = j >> 1;
        const int y1 = min(y0 + 1, Hh - 1);
        const float* r0 = sL + y0 * Ww;
        const float* r1 = sL + y1 * Ww;
        const bool vodd = (j & 1) != 0;

        const int i0 = (ox > 0) ? (ox - 1) : 0;   // pixel k=0
        float v[4];
        int ii[4] = { i0, ox, ox + 1, ox + 2 };
        if (!vodd) {
            #pragma unroll
            for (int k = 0; k < 4; k++) {
                int x0 = ii[k] >> 1;
                int x1 = min(x0 + 1, Ww - 1);
                float a = r0[x0];
                v[k] = (ii[k] & 1) ? 0.5f * (a + r0[x1]) : a;
            }
        } else {
            #pragma unroll
            for (int k = 0; k < 4; k++) {
                int x0 = ii[k] >> 1;
                int x1 = min(x0 + 1, Ww - 1);
                float a = r0[x0], b = r1[x0];
                v[k] = (ii[k] & 1) ? 0.25f * ((a + r0[x1]) + (b + r1[x1]))
                                   : 0.5f  * (a + b);
            }
        }

        const float4 t4 = *(const float4*)&T[oy * OW + ox];
        const float tv[4] = { t4.x, t4.y, t4.z, t4.w };
        #pragma unroll
        for (int k = 0; k < 4; k++) {
            float s = __fdividef(1.0f, 1.0f + __expf(-v[k]));
            si = fmaf(s, tv[k], si);
            sx = fmaf(s, s, sx);
            st = fmaf(tv[k], tv[k], st);
        }
    }

    __shared__ float sm[3][8];
    int lane = threadIdx.x & 31;
    int wid  = threadIdx.x >> 5;
    #pragma unroll
    for (int o = 16; o; o >>= 1) {
        si += __shfl_down_sync(0xffffffffu, si, o);
        sx += __shfl_down_sync(0xffffffffu, sx, o);
        st += __shfl_down_sync(0xffffffffu, st, o);
    }
    if (lane == 0) { sm[0][wid] = si; sm[1][wid] = sx; sm[2][wid] = st; }
    __syncthreads();
    if (wid == 0) {
        si = (lane < 8) ? sm[0][lane] : 0.0f;
        sx = (lane < 8) ? sm[1][lane] : 0.0f;
        st = (lane < 8) ? sm[2][lane] : 0.0f;
        #pragma unroll
        for (int o = 4; o; o >>= 1) {
            si += __shfl_down_sync(0xffffffffu, si, o);
            sx += __shfl_down_sync(0xffffffffu, sx, o);
            st += __shfl_down_sync(0xffffffffu, st, o);
        }
        if (lane == 0) {
            g_inter[inst] = si;
            g_ux[inst]    = sx;
            g_ut[inst]    = st;
        }
    }
}

__global__ __launch_bounds__(512) void loss_kernel(float* __restrict__ out, int n)
{
    __shared__ float sm[16];
    float acc = 0.0f;
    for (int i = threadIdx.x; i < n; i += 512) {
        float u = g_ux[i] + g_ut[i] + 1e-5f;
        acc += 1.0f - 2.0f * g_inter[i] / u;
    }
    int lane = threadIdx.x & 31;
    int wid  = threadIdx.x >> 5;
    #pragma unroll
    for (int o = 16; o; o >>= 1) acc += __shfl_down_sync(0xffffffffu, acc, o);
    if (lane == 0) sm[wid] = acc;
    __syncthreads();
    if (wid == 0) {
        acc = (lane < 16) ? sm[lane] : 0.0f;
        #pragma unroll
        for (int o = 8; o; o >>= 1) acc += __shfl_down_sync(0xffffffffu, acc, o);
        if (lane == 0) out[0] = acc / (float)n;
    }
}

extern "C" void kernel_launch(void* const* d_in, const int* in_sizes, int n_in,
                              void* d_out, int out_size)
{
    const float* feats   = (const float*)d_in[0];
    const float* params  = (const float*)d_in[1];
    const float* locs    = (const float*)d_in[2];
    const float* gt      = (const float*)d_in[3];
    const int*   im_inds = (const int*)d_in[4];
    const int*   fpn     = (const int*)d_in[5];

    int n = in_sizes[1] / NP;
    if (n > MAXI) n = MAXI;

    cudaFuncSetAttribute(dice_kernel, cudaFuncAttributeMaxDynamicSharedMemorySize,
                         HW * (int)sizeof(float));

    logits_kernel<<<n, 256>>>(feats, params, locs, im_inds, fpn);
    dice_kernel<<<n, 256, HW * sizeof(float)>>>(gt);
    loss_kernel<<<1, 512>>>((float*)d_out, n);
}

// round 3
// speedup vs baseline: 2.2228x; 1.5333x over previous
#include <cuda_runtime.h>

#define Hh 100
#define Ww 136
#define HW (Hh * Ww)        // 13600
#define OH (2 * Hh)         // 200
#define OW (2 * Ww)         // 272
#define OHW (OH * OW)       // 54400
#define NP 169
#define MAXI 512

typedef unsigned long long ull;

__device__ float g_logits[MAXI * HW];
__device__ float g_inter[MAXI];
__device__ float g_ux[MAXI];
__device__ float g_ut[MAXI];

// ---- packed f32x2 helpers (sm_100+) ----
__device__ __forceinline__ ull pk2(float lo, float hi) {
    ull r; asm("mov.b64 %0, {%1,%2};" : "=l"(r) : "f"(lo), "f"(hi)); return r;
}
__device__ __forceinline__ ull fma2(ull a, ull b, ull c) {
    ull d; asm("fma.rn.f32x2 %0, %1, %2, %3;" : "=l"(d) : "l"(a), "l"(b), "l"(c)); return d;
}
__device__ __forceinline__ ull relu2(ull a) {
    float x, y;
    asm("mov.b64 {%0,%1}, %2;" : "=f"(x), "=f"(y) : "l"(a));
    x = fmaxf(x, 0.0f); y = fmaxf(y, 0.0f);
    ull r; asm("mov.b64 %0, {%1,%2};" : "=l"(r) : "f"(x), "f"(y)); return r;
}
__device__ __forceinline__ void upk2(ull a, float& x, float& y) {
    asm("mov.b64 {%0,%1}, %2;" : "=f"(x), "=f"(y) : "l"(a));
}

// ---------------------------------------------------------------------------
// Kernel A: dynamic mask head -> logits. One block per instance.
// 4 pixels/thread as two f32x2 pairs; weights pre-duplicated (lo=hi) in SMEM,
// fetched as LDS.128. NO min-blocks cap: let regs float (spills cost far more
// than occupancy here — measured R2).
// ---------------------------------------------------------------------------
__global__ __launch_bounds__(256) void logits_kernel(
    const float* __restrict__ feats,
    const float* __restrict__ params,
    const float* __restrict__ locs,
    const int*   __restrict__ im_inds,
    const int*   __restrict__ fpn)
{
    const int inst = blockIdx.x;
    const int tid  = threadIdx.x;

    __shared__ __align__(16) ull sw0[8][12];
    __shared__ __align__(16) ull sw1[8][10];
    __shared__ __align__(16) ull sw2[10];

    for (int i = tid; i < NP; i += 256) {
        float w = params[inst * NP + i];
        ull d = pk2(w, w);
        if      (i < 80)  sw0[i / 10][i % 10] = d;
        else if (i < 144) { int k = i - 80; sw1[k >> 3][k & 7] = d; }
        else if (i < 152) sw2[i - 144] = d;
        else if (i < 160) sw0[i - 152][10] = d;
        else if (i < 168) sw1[i - 160][8] = d;
        else              sw2[8] = d;
    }
    __syncthreads();

    const float cx = locs[inst * 2 + 0];
    const float cy = locs[inst * 2 + 1];
    const float inv_soi = 1.0f / (float)(8 << fpn[inst]);
    const float step = -8.0f * inv_soi;
    const float* __restrict__ fb = feats + (size_t)im_inds[inst] * 8 * HW;
    float* __restrict__ Lg = g_logits + (size_t)inst * HW;

    const int NQ = HW / 4;   // 3400; Ww%4==0 so quads never cross rows
    for (int q = tid; q < NQ; q += 256) {
        const int p  = q * 4;
        const int py = p / Ww;
        const int px = p - py * Ww;
        const float dyv = (cy - (float)(py * 8 + 4)) * inv_soi;
        const float dxb = (cx - (float)(px * 8 + 4)) * inv_soi;
        const ull dy2 = pk2(dyv, dyv);
        const ull dx0 = pk2(dxb, dxb + step);
        const ull dx1 = pk2(dxb + 2.0f * step, dxb + 3.0f * step);

        ull f0[8], f1[8];
        #pragma unroll
        for (int c = 0; c < 8; c++) {
            float4 v = *(const float4*)&fb[c * HW + p];
            f0[c] = pk2(v.x, v.y);
            f1[c] = pk2(v.z, v.w);
        }

        // layer 0: 10 -> 8, relu
        ull h0a[8], h0b[8];
        #pragma unroll
        for (int j = 0; j < 8; j++) {
            const ulonglong2* r = (const ulonglong2*)sw0[j];
            ulonglong2 wA = r[0], wB = r[1], wC = r[2], wD = r[3], wE = r[4];
            ull bias = sw0[j][10];
            ull a0 = fma2(wA.y, dy2, bias);  a0 = fma2(wA.x, dx0, a0);
            ull a1 = fma2(wA.y, dy2, bias);  a1 = fma2(wA.x, dx1, a1);
            a0 = fma2(wB.x, f0[0], a0);  a1 = fma2(wB.x, f1[0], a1);
            a0 = fma2(wB.y, f0[1], a0);  a1 = fma2(wB.y, f1[1], a1);
            a0 = fma2(wC.x, f0[2], a0);  a1 = fma2(wC.x, f1[2], a1);
            a0 = fma2(wC.y, f0[3], a0);  a1 = fma2(wC.y, f1[3], a1);
            a0 = fma2(wD.x, f0[4], a0);  a1 = fma2(wD.x, f1[4], a1);
            a0 = fma2(wD.y, f0[5], a0);  a1 = fma2(wD.y, f1[5], a1);
            a0 = fma2(wE.x, f0[6], a0);  a1 = fma2(wE.x, f1[6], a1);
            a0 = fma2(wE.y, f0[7], a0);  a1 = fma2(wE.y, f1[7], a1);
            h0a[j] = relu2(a0);
            h0b[j] = relu2(a1);
        }

        // layer 1: 8 -> 8, relu
        ull h1a[8], h1b[8];
        #pragma unroll
        for (int j = 0; j < 8; j++) {
            const ulonglong2* r = (const ulonglong2*)sw1[j];
            ulonglong2 wA = r[0], wB = r[1], wC = r[2], wD = r[3];
            ull bias = sw1[j][8];
            ull a0 = fma2(wA.x, h0a[0], bias);  ull a1 = fma2(wA.x, h0b[0], bias);
            a0 = fma2(wA.y, h0a[1], a0);  a1 = fma2(wA.y, h0b[1], a1);
            a0 = fma2(wB.x, h0a[2], a0);  a1 = fma2(wB.x, h0b[2], a1);
            a0 = fma2(wB.y, h0a[3], a0);  a1 = fma2(wB.y, h0b[3], a1);
            a0 = fma2(wC.x, h0a[4], a0);  a1 = fma2(wC.x, h0b[4], a1);
            a0 = fma2(wC.y, h0a[5], a0);  a1 = fma2(wC.y, h0b[5], a1);
            a0 = fma2(wD.x, h0a[6], a0);  a1 = fma2(wD.x, h0b[6], a1);
            a0 = fma2(wD.y, h0a[7], a0);  a1 = fma2(wD.y, h0b[7], a1);
            h1a[j] = relu2(a0);
            h1b[j] = relu2(a1);
        }

        // layer 2: 8 -> 1
        {
            const ulonglong2* r = (const ulonglong2*)sw2;
            ulonglong2 wA = r[0], wB = r[1], wC = r[2], wD = r[3];
            ull bias = sw2[8];
            ull a0 = fma2(wA.x, h1a[0], bias);  ull a1 = fma2(wA.x, h1b[0], bias);
            a0 = fma2(wA.y, h1a[1], a0);  a1 = fma2(wA.y, h1b[1], a1);
            a0 = fma2(wB.x, h1a[2], a0);  a1 = fma2(wB.x, h1b[2], a1);
            a0 = fma2(wB.y, h1a[3], a0);  a1 = fma2(wB.y, h1b[3], a1);
            a0 = fma2(wC.x, h1a[4], a0);  a1 = fma2(wC.x, h1b[4], a1);
            a0 = fma2(wC.y, h1a[5], a0);  a1 = fma2(wC.y, h1b[5], a1);
            a0 = fma2(wD.x, h1a[6], a0);  a1 = fma2(wD.x, h1b[6], a1);
            a0 = fma2(wD.y, h1a[7], a0);  a1 = fma2(wD.y, h1b[7], a1);
            float4 o;
            upk2(a0, o.x, o.y);
            upk2(a1, o.z, o.w);
            *(float4*)&Lg[p] = o;
        }
    }
}

// ---------------------------------------------------------------------------
// Kernel B: 2x aligned-bilinear + sigmoid + dice partials.
// One block per instance; logit tile in dynamic SMEM; 512 threads (exactly
// 4 blocks/SM at 54.4KB smem = 2048 threads/SM); streaming gt loads.
// ---------------------------------------------------------------------------
__global__ __launch_bounds__(512) void dice_kernel(const float* __restrict__ gt)
{
    extern __shared__ float sL[];   // HW floats = 54.4 KB
    const int inst = blockIdx.x;
    const float* __restrict__ L = g_logits + (size_t)inst * HW;
    const float* __restrict__ T = gt + (size_t)inst * OHW;

    for (int i = threadIdx.x; i < HW; i += 512) sL[i] = L[i];
    __syncthreads();

    float si = 0.0f, sx = 0.0f, st = 0.0f;

    const int NQ = OHW / 4;       // 13600 (OW%4==0)
    for (int q = threadIdx.x; q < NQ; q += 512) {
        const int oy = q / (OW / 4);
        const int ox = (q - oy * (OW / 4)) * 4;
        const int j  = (oy > 0) ? (oy - 1) : 0;
        const int y0 = j >> 1;
        const int y1 = min(y0 + 1, Hh - 1);
        const float* r0 = sL + y0 * Ww;
        const float* r1 = sL + y1 * Ww;
        const bool vodd = (j & 1) != 0;

        const int i0 = (ox > 0) ? (ox - 1) : 0;
        float v[4];
        int ii[4] = { i0, ox, ox + 1, ox + 2 };
        if (!vodd) {
            #pragma unroll
            for (int k = 0; k < 4; k++) {
                int x0 = ii[k] >> 1;
                int x1 = min(x0 + 1, Ww - 1);
                float a = r0[x0];
                v[k] = (ii[k] & 1) ? 0.5f * (a + r0[x1]) : a;
            }
        } else {
            #pragma unroll
            for (int k = 0; k < 4; k++) {
                int x0 = ii[k] >> 1;
                int x1 = min(x0 + 1, Ww - 1);
                float a = r0[x0], b = r1[x0];
                v[k] = (ii[k] & 1) ? 0.25f * ((a + r0[x1]) + (b + r1[x1]))
                                   : 0.5f  * (a + b);
            }
        }

        const float4 t4 = __ldcs((const float4*)&T[oy * OW + ox]);
        const float tv[4] = { t4.x, t4.y, t4.z, t4.w };
        #pragma unroll
        for (int k = 0; k < 4; k++) {
            float s = __fdividef(1.0f, 1.0f + __expf(-v[k]));
            si = fmaf(s, tv[k], si);
            sx = fmaf(s, s, sx);
            st = fmaf(tv[k], tv[k], st);
        }
    }

    __shared__ float sm[3][16];
    int lane = threadIdx.x & 31;
    int wid  = threadIdx.x >> 5;
    #pragma unroll
    for (int o = 16; o; o >>= 1) {
        si += __shfl_down_sync(0xffffffffu, si, o);
        sx += __shfl_down_sync(0xffffffffu, sx, o);
        st += __shfl_down_sync(0xffffffffu, st, o);
    }
    if (lane == 0) { sm[0][wid] = si; sm[1][wid] = sx; sm[2][wid] = st; }
    __syncthreads();
    if (wid == 0) {
        si = (lane < 16) ? sm[0][lane] : 0.0f;
        sx = (lane < 16) ? sm[1][lane] : 0.0f;
        st = (lane < 16) ? sm[2][lane] : 0.0f;
        #pragma unroll
        for (int o = 8; o; o >>= 1) {
            si += __shfl_down_sync(0xffffffffu, si, o);
            sx += __shfl_down_sync(0xffffffffu, sx, o);
            st += __shfl_down_sync(0xffffffffu, st, o);
        }
        if (lane == 0) {
            g_inter[inst] = si;
            g_ux[inst]    = sx;
            g_ut[inst]    = st;
        }
    }
}

__global__ __launch_bounds__(512) void loss_kernel(float* __restrict__ out, int n)
{
    __shared__ float sm[16];
    float acc = 0.0f;
    for (int i = threadIdx.x; i < n; i += 512) {
        float u = g_ux[i] + g_ut[i] + 1e-5f;
        acc += 1.0f - 2.0f * g_inter[i] / u;
    }
    int lane = threadIdx.x & 31;
    int wid  = threadIdx.x >> 5;
    #pragma unroll
    for (int o = 16; o; o >>= 1) acc += __shfl_down_sync(0xffffffffu, acc, o);
    if (lane == 0) sm[wid] = acc;
    __syncthreads();
    if (wid == 0) {
        acc = (lane < 16) ? sm[lane] : 0.0f;
        #pragma unroll
        for (int o = 8; o; o >>= 1) acc += __shfl_down_sync(0xffffffffu, acc, o);
        if (lane == 0) out[0] = acc / (float)n;
    }
}

extern "C" void kernel_launch(void* const* d_in, const int* in_sizes, int n_in,
                              void* d_out, int out_size)
{
    const float* feats   = (const float*)d_in[0];
    const float* params  = (const float*)d_in[1];
    const float* locs    = (const float*)d_in[2];
    const float* gt      = (const float*)d_in[3];
    const int*   im_inds = (const int*)d_in[4];
    const int*   fpn     = (const int*)d_in[5];

    int n = in_sizes[1] / NP;
    if (n > MAXI) n = MAXI;

    cudaFuncSetAttribute(dice_kernel, cudaFuncAttributeMaxDynamicSharedMemorySize,
                         HW * (int)sizeof(float));

    logits_kernel<<<n, 256>>>(feats, params, locs, im_inds, fpn);
    dice_kernel<<<n, 512, HW * sizeof(float)>>>(gt);
    loss_kernel<<<1, 512>>>((float*)d_out, n);
}